// round 4
// baseline (speedup 1.0000x reference)
#include <cuda_runtime.h>
#include <cuda_bf16.h>

#define N_NODES 16384
#define E_RAW   262144
#define E_TOT   (E_RAW + N_NODES)   // 278528 with self loops
#define H1      256
#define D2      512                  // 2*H1 = gat1 out channels = gat2 channels

// ---------------- scratch (device globals; no allocation allowed) -------------
__device__ float g_h0  [N_NODES * H1];   // fc output (relu)           16 MB
__device__ float g_g1  [N_NODES * D2];   // gat1 pre-agg features      32 MB
__device__ float g_out1[N_NODES * D2];   // gat1 output (relu)         32 MB
__device__ float g_g2  [N_NODES * D2];   // gat2 pre-agg features      32 MB
__device__ float g_al1s[N_NODES * 2];
__device__ float g_al1d[N_NODES * 2];
__device__ float g_al2s[N_NODES];
__device__ float g_al2d[N_NODES];
__device__ int   g_deg [N_NODES];
__device__ int   g_cur [N_NODES];
__device__ int   g_off [N_NODES + 1];
__device__ int   g_esrc[E_TOT];

// buffer selector (device-side; avoids any host cudaGetSymbolAddress)
__device__ __forceinline__ float* buf_sel(int id) {
    switch (id) {
        case 0: return g_h0;
        case 1: return g_g1;
        case 2: return g_out1;
        case 3: return g_g2;
    }
    return nullptr;
}

// ------------------------------- CSR build -----------------------------------
__global__ void zero_kernel() {
    int i = blockIdx.x * blockDim.x + threadIdx.x;
    if (i < N_NODES) { g_deg[i] = 0; g_cur[i] = 0; }
}

// adj is int32: adj[0..E_RAW) = src, adj[E_RAW..2*E_RAW) = dst
__global__ void hist_kernel(const int* __restrict__ adj) {
    int i = blockIdx.x * blockDim.x + threadIdx.x;
    if (i >= E_TOT) return;
    int dst = (i < E_RAW) ? adj[E_RAW + i] : (i - E_RAW);
    atomicAdd(&g_deg[dst], 1);
}

// single block, 1024 threads, 16 elements each -> exclusive scan of g_deg
__global__ void scan_kernel() {
    __shared__ int partial[1024];
    int t = threadIdx.x;
    int base = t * 16;
    int local[16];
    int s = 0;
#pragma unroll
    for (int i = 0; i < 16; i++) { local[i] = s; s += g_deg[base + i]; }
    partial[t] = s;
    __syncthreads();
    for (int off = 1; off < 1024; off <<= 1) {
        int v = (t >= off) ? partial[t - off] : 0;
        __syncthreads();
        partial[t] += v;
        __syncthreads();
    }
    int pre = (t == 0) ? 0 : partial[t - 1];
#pragma unroll
    for (int i = 0; i < 16; i++) g_off[base + i] = pre + local[i];
    if (t == 1023) g_off[N_NODES] = partial[1023];
}

__global__ void scatter_kernel(const int* __restrict__ adj) {
    int i = blockIdx.x * blockDim.x + threadIdx.x;
    if (i >= E_TOT) return;
    int src, dst;
    if (i < E_RAW) { src = adj[i]; dst = adj[E_RAW + i]; }
    else           { src = i - E_RAW;  dst = i - E_RAW; }
    int pos = g_off[dst] + atomicAdd(&g_cur[dst], 1);
    g_esrc[pos] = src;
}

// ------------------------------- SGEMM 128x128 --------------------------------
// C[M,N] = A[M,K] * B[K,N], row-major everywhere. M%128==0, N%128==0, K%16==0.
// a_sel < 0: use A_ext; else scratch buffer id. C always a scratch buffer id.
// RELU_BIAS: epilogue v = relu(v + bias[n])
template <int RELU_BIAS>
__global__ __launch_bounds__(256, 2) void sgemm128(
    const float* __restrict__ A_ext, int a_sel,
    const float* __restrict__ B,
    const float* __restrict__ bias, int c_sel,
    int M, int N, int K)
{
    const float* A = (a_sel < 0) ? A_ext : buf_sel(a_sel);
    float* C = buf_sel(c_sel);

    __shared__ float As[16 * 128];
    __shared__ float Bs[16 * 128];
    const int tid = threadIdx.x;
    const int tx = tid & 15, ty = tid >> 4;
    const int mBase = blockIdx.y * 128, nBase = blockIdx.x * 128;

    float acc[8][8] = {};

    for (int k0 = 0; k0 < K; k0 += 16) {
        // load A tile 128x16 (512 float4), store transposed As[k][m]
#pragma unroll
        for (int l = 0; l < 2; l++) {
            int idx = tid + l * 256;
            int r = idx >> 2, c4 = idx & 3;
            float4 v = *(const float4*)&A[(size_t)(mBase + r) * K + k0 + c4 * 4];
            As[(c4 * 4 + 0) * 128 + r] = v.x;
            As[(c4 * 4 + 1) * 128 + r] = v.y;
            As[(c4 * 4 + 2) * 128 + r] = v.z;
            As[(c4 * 4 + 3) * 128 + r] = v.w;
        }
        // load B tile 16x128 (512 float4)
#pragma unroll
        for (int l = 0; l < 2; l++) {
            int idx = tid + l * 256;
            int r = idx >> 5, c4 = idx & 31;
            *(float4*)&Bs[r * 128 + c4 * 4] =
                *(const float4*)&B[(size_t)(k0 + r) * N + nBase + c4 * 4];
        }
        __syncthreads();
#pragma unroll
        for (int k = 0; k < 16; k++) {
            float a[8], b[8];
#pragma unroll
            for (int i = 0; i < 8; i++) a[i] = As[k * 128 + ty * 8 + i];
#pragma unroll
            for (int j = 0; j < 8; j++) b[j] = Bs[k * 128 + tx * 8 + j];
#pragma unroll
            for (int i = 0; i < 8; i++)
#pragma unroll
                for (int j = 0; j < 8; j++) acc[i][j] += a[i] * b[j];
        }
        __syncthreads();
    }

#pragma unroll
    for (int i = 0; i < 8; i++) {
        int m = mBase + ty * 8 + i;
#pragma unroll
        for (int j = 0; j < 8; j++) {
            int n = nBase + tx * 8 + j;
            float v = acc[i][j];
            if (RELU_BIAS) { v += bias[n]; v = v > 0.f ? v : 0.f; }
            C[(size_t)m * N + n] = v;
        }
    }
}

// --------------------------- attention logits ---------------------------------
// gat1: 2 heads. g1[n, 0:256] is head0, g1[n, 256:512] is head1.
__global__ void al1_kernel(const float* __restrict__ a_src,
                           const float* __restrict__ a_dst)
{
    const float* g1 = g_g1;
    int n = blockIdx.x, t = threadIdx.x;  // 256 threads
    float v0 = g1[(size_t)n * D2 + t];
    float v1 = g1[(size_t)n * D2 + 256 + t];
    float s0 = v0 * a_src[t],       d0 = v0 * a_dst[t];
    float s1 = v1 * a_src[256 + t], d1 = v1 * a_dst[256 + t];
#pragma unroll
    for (int o = 16; o; o >>= 1) {
        s0 += __shfl_down_sync(0xffffffffu, s0, o);
        d0 += __shfl_down_sync(0xffffffffu, d0, o);
        s1 += __shfl_down_sync(0xffffffffu, s1, o);
        d1 += __shfl_down_sync(0xffffffffu, d1, o);
    }
    __shared__ float sh[4][8];
    int w = t >> 5, l = t & 31;
    if (l == 0) { sh[0][w] = s0; sh[1][w] = d0; sh[2][w] = s1; sh[3][w] = d1; }
    __syncthreads();
    if (t < 4) {
        float acc = 0.f;
#pragma unroll
        for (int w2 = 0; w2 < 8; w2++) acc += sh[t][w2];
        if (t == 0) g_al1s[n * 2 + 0] = acc;
        if (t == 1) g_al1d[n * 2 + 0] = acc;
        if (t == 2) g_al1s[n * 2 + 1] = acc;
        if (t == 3) g_al1d[n * 2 + 1] = acc;
    }
}

// gat2: 1 head over 512 channels.
__global__ void al2_kernel(const float* __restrict__ a_src,
                           const float* __restrict__ a_dst)
{
    const float* g2 = g_g2;
    int n = blockIdx.x, t = threadIdx.x;  // 256 threads
    float v0 = g2[(size_t)n * D2 + t];
    float v1 = g2[(size_t)n * D2 + 256 + t];
    float s = v0 * a_src[t] + v1 * a_src[256 + t];
    float d = v0 * a_dst[t] + v1 * a_dst[256 + t];
#pragma unroll
    for (int o = 16; o; o >>= 1) {
        s += __shfl_down_sync(0xffffffffu, s, o);
        d += __shfl_down_sync(0xffffffffu, d, o);
    }
    __shared__ float sh[2][8];
    int w = t >> 5, l = t & 31;
    if (l == 0) { sh[0][w] = s; sh[1][w] = d; }
    __syncthreads();
    if (t < 2) {
        float acc = 0.f;
#pragma unroll
        for (int w2 = 0; w2 < 8; w2++) acc += sh[t][w2];
        if (t == 0) g_al2s[n] = acc;
        else        g_al2d[n] = acc;
    }
}

// --------------------------- GAT aggregation ----------------------------------
// Softmax without max subtraction: logits are O(+-5), exp cannot overflow, and
// alpha is mathematically identical. One CTA (256 threads) per dst node.
__global__ void gat1_agg(const float* __restrict__ bias)  // b1[512] -> g_out1
{
    const float* h = g_g1;
    float* out = g_out1;
    int d = blockIdx.x, t = threadIdx.x;
    __shared__ float sw0[256], sw1[256];
    __shared__ int   ss[256];
    int start = g_off[d], end = g_off[d + 1];
    float ad0 = g_al1d[d * 2 + 0], ad1 = g_al1d[d * 2 + 1];
    float acc0 = 0.f, acc1 = 0.f, den0 = 0.f, den1 = 0.f;
    for (int base = start; base < end; base += 256) {
        int m = min(256, end - base);
        if (t < m) {
            int s = g_esrc[base + t];
            float e0 = g_al1s[s * 2 + 0] + ad0; e0 = e0 > 0.f ? e0 : 0.2f * e0;
            float e1 = g_al1s[s * 2 + 1] + ad1; e1 = e1 > 0.f ? e1 : 0.2f * e1;
            sw0[t] = __expf(e0);
            sw1[t] = __expf(e1);
            ss[t] = s;
        }
        __syncthreads();
        for (int j = 0; j < m; j++) {
            int s = ss[j];
            float w0 = sw0[j], w1 = sw1[j];
            acc0 += w0 * h[(size_t)s * D2 + t];
            acc1 += w1 * h[(size_t)s * D2 + 256 + t];
            den0 += w0; den1 += w1;
        }
        __syncthreads();
    }
    float o0 = acc0 / (den0 + 1e-16f) + bias[t];
    float o1 = acc1 / (den1 + 1e-16f) + bias[256 + t];
    out[(size_t)d * D2 + t]       = o0 > 0.f ? o0 : 0.f;
    out[(size_t)d * D2 + 256 + t] = o1 > 0.f ? o1 : 0.f;
}

__global__ void gat2_agg(const float* __restrict__ bias,  // b2[512]
                         float* __restrict__ out)         // d_out (relu applied)
{
    const float* h = g_g2;
    int d = blockIdx.x, t = threadIdx.x;
    __shared__ float sw[256];
    __shared__ int   ss[256];
    int start = g_off[d], end = g_off[d + 1];
    float ad = g_al2d[d];
    float acc0 = 0.f, acc1 = 0.f, den = 0.f;
    for (int base = start; base < end; base += 256) {
        int m = min(256, end - base);
        if (t < m) {
            int s = g_esrc[base + t];
            float e = g_al2s[s] + ad; e = e > 0.f ? e : 0.2f * e;
            sw[t] = __expf(e);
            ss[t] = s;
        }
        __syncthreads();
        for (int j = 0; j < m; j++) {
            int s = ss[j];
            float w = sw[j];
            acc0 += w * h[(size_t)s * D2 + t];
            acc1 += w * h[(size_t)s * D2 + 256 + t];
            den += w;
        }
        __syncthreads();
    }
    float r = 1.f / (den + 1e-16f);
    float o0 = acc0 * r + bias[t];
    float o1 = acc1 * r + bias[256 + t];
    out[(size_t)d * D2 + t]       = o0 > 0.f ? o0 : 0.f;
    out[(size_t)d * D2 + 256 + t] = o1 > 0.f ? o1 : 0.f;
}

// ------------------------------- launch ---------------------------------------
extern "C" void kernel_launch(void* const* d_in, const int* in_sizes, int n_in,
                              void* d_out, int out_size)
{
    const float* x     = (const float*)d_in[0];
    const int*   adj   = (const int*)d_in[1];     // int32 (JAX x64 disabled)
    const float* W_fc  = (const float*)d_in[2];
    const float* b_fc  = (const float*)d_in[3];
    const float* W1    = (const float*)d_in[4];
    const float* a1s   = (const float*)d_in[5];
    const float* a1d   = (const float*)d_in[6];
    const float* b1    = (const float*)d_in[7];
    const float* W2    = (const float*)d_in[8];
    const float* a2s   = (const float*)d_in[9];
    const float* a2d   = (const float*)d_in[10];
    const float* b2    = (const float*)d_in[11];
    float*       out   = (float*)d_out;

    // CSR build
    zero_kernel<<<64, 256>>>();
    hist_kernel<<<(E_TOT + 255) / 256, 256>>>(adj);
    scan_kernel<<<1, 1024>>>();
    scatter_kernel<<<(E_TOT + 255) / 256, 256>>>(adj);

    // fc: g_h0 = relu(x @ W_fc + b_fc)   [16384,256]
    sgemm128<1><<<dim3(H1 / 128, N_NODES / 128), 256>>>(x, -1, W_fc, b_fc, 0,
                                                        N_NODES, H1, H1);
    // gat1 features: g_g1 = g_h0 @ W1    [16384,512]
    sgemm128<0><<<dim3(D2 / 128, N_NODES / 128), 256>>>(nullptr, 0, W1, nullptr, 1,
                                                        N_NODES, D2, H1);
    al1_kernel<<<N_NODES, 256>>>(a1s, a1d);
    gat1_agg<<<N_NODES, 256>>>(b1);

    // gat2 features: g_g2 = g_out1 @ W2  [16384,512]
    sgemm128<0><<<dim3(D2 / 128, N_NODES / 128), 256>>>(nullptr, 2, W2, nullptr, 3,
                                                        N_NODES, D2, D2);
    al2_kernel<<<N_NODES, 256>>>(a2s, a2d);
    gat2_agg<<<N_NODES, 256>>>(b2, out);
}

// round 7
// speedup vs baseline: 2.0989x; 2.0989x over previous
#include <cuda_runtime.h>
#include <cuda_bf16.h>
#include <cstdint>

#define N_NODES 16384
#define E_RAW   262144
#define E_TOT   (E_RAW + N_NODES)   // 278528 with self loops
#define H1      256
#define D2      512                  // 2*H1 = gat1 out channels = gat2 channels

// ---------------- scratch (device globals; no allocation allowed) -------------
__device__ float g_h0  [N_NODES * H1];   // fc output (relu)           16 MB
__device__ float g_g1  [N_NODES * D2];   // gat1 pre-agg features      32 MB
__device__ float g_out1[N_NODES * D2];   // gat1 output (relu)         32 MB
__device__ float g_g2  [N_NODES * D2];   // gat2 pre-agg features      32 MB
__device__ float g_al1s[N_NODES * 2];
__device__ float g_al1d[N_NODES * 2];
__device__ float g_al2s[N_NODES];
__device__ float g_al2d[N_NODES];
__device__ int   g_deg [N_NODES];
__device__ int   g_cur [N_NODES];
__device__ int   g_off [N_NODES + 1];
__device__ int   g_esrc[E_TOT];

// buffer selector (device-side; avoids any host cudaGetSymbolAddress)
__device__ __forceinline__ float* buf_sel(int id) {
    switch (id) {
        case 0: return g_h0;
        case 1: return g_g1;
        case 2: return g_out1;
        case 3: return g_g2;
    }
    return nullptr;
}

// ------------------------------- CSR build -----------------------------------
__global__ void zero_kernel() {
    int i = blockIdx.x * blockDim.x + threadIdx.x;
    if (i < N_NODES) { g_deg[i] = 0; g_cur[i] = 0; }
}

// adj is int32: adj[0..E_RAW) = src, adj[E_RAW..2*E_RAW) = dst
__global__ void hist_kernel(const int* __restrict__ adj) {
    int i = blockIdx.x * blockDim.x + threadIdx.x;
    if (i >= E_TOT) return;
    int dst = (i < E_RAW) ? adj[E_RAW + i] : (i - E_RAW);
    atomicAdd(&g_deg[dst], 1);
}

// single block, 1024 threads, 16 elements each -> exclusive scan of g_deg
__global__ void scan_kernel() {
    __shared__ int partial[1024];
    int t = threadIdx.x;
    int base = t * 16;
    int local[16];
    int s = 0;
#pragma unroll
    for (int i = 0; i < 16; i++) { local[i] = s; s += g_deg[base + i]; }
    partial[t] = s;
    __syncthreads();
    for (int off = 1; off < 1024; off <<= 1) {
        int v = (t >= off) ? partial[t - off] : 0;
        __syncthreads();
        partial[t] += v;
        __syncthreads();
    }
    int pre = (t == 0) ? 0 : partial[t - 1];
#pragma unroll
    for (int i = 0; i < 16; i++) g_off[base + i] = pre + local[i];
    if (t == 1023) g_off[N_NODES] = partial[1023];
}

__global__ void scatter_kernel(const int* __restrict__ adj) {
    int i = blockIdx.x * blockDim.x + threadIdx.x;
    if (i >= E_TOT) return;
    int src, dst;
    if (i < E_RAW) { src = adj[i]; dst = adj[E_RAW + i]; }
    else           { src = i - E_RAW;  dst = i - E_RAW; }
    int pos = g_off[dst] + atomicAdd(&g_cur[dst], 1);
    g_esrc[pos] = src;
}

// --------------------------- TF32 tensor-core GEMM ----------------------------
// C[M,N] = A[M,K] * B[K,N], row-major. M%128==0, N%128==0, K%32==0.
// CTA tile 128x128, 8 warps, warp tile 64x32, mma.sync m16n8k8 tf32.
__device__ __forceinline__ uint32_t f2tf32(float x) {
    uint32_t u;
    asm("cvt.rna.tf32.f32 %0, %1;" : "=r"(u) : "f"(x));
    return u;
}

#define AS_STRIDE 36
#define BS_STRIDE 136

template <int RELU_BIAS>
__global__ __launch_bounds__(256) void gemm_tf32(
    const float* __restrict__ A_ext, int a_sel,
    const float* __restrict__ B,
    const float* __restrict__ bias, int c_sel,
    int M, int N, int K)
{
    const float* A = (a_sel < 0) ? A_ext : buf_sel(a_sel);
    float* C = buf_sel(c_sel);

    __shared__ float As[128 * AS_STRIDE];   // [m][k], k-step 32, pad->36
    __shared__ float Bs[32 * BS_STRIDE];    // [k][n], n 128, pad->136

    const int tid  = threadIdx.x;
    const int lane = tid & 31;
    const int wid  = tid >> 5;
    const int q = lane >> 2;     // 0..7
    const int r = lane & 3;      // 0..3
    const int wm = (wid >> 2) * 64;   // warp m offset: 0 or 64
    const int wn = (wid & 3) * 32;    // warp n offset: 0,32,64,96

    const int mBase = blockIdx.y * 128, nBase = blockIdx.x * 128;

    float c[4][4][4];
#pragma unroll
    for (int i = 0; i < 4; i++)
#pragma unroll
        for (int j = 0; j < 4; j++)
#pragma unroll
            for (int u = 0; u < 4; u++) c[i][j][u] = 0.f;

    // prefetch registers
    float4 pa[4], pb[4];

    // A tile load pattern: idx = tid + 256*l; row = idx>>3 (0..127), c4 = idx&7
    // B tile load pattern: idx = tid + 256*l; kk = idx>>5 (0..31), n4 = idx&31
#pragma unroll
    for (int l = 0; l < 4; l++) {
        int idx = tid + l * 256;
        int row = idx >> 3, c4 = idx & 7;
        pa[l] = *(const float4*)&A[(size_t)(mBase + row) * K + c4 * 4];
        int kk = idx >> 5, n4 = idx & 31;
        pb[l] = *(const float4*)&B[(size_t)kk * N + nBase + n4 * 4];
    }

    for (int k0 = 0; k0 < K; k0 += 32) {
        // store prefetched tile to smem with tf32 rounding
#pragma unroll
        for (int l = 0; l < 4; l++) {
            int idx = tid + l * 256;
            int row = idx >> 3, c4 = idx & 7;
            float* ap = &As[row * AS_STRIDE + c4 * 4];
            ap[0] = __uint_as_float(f2tf32(pa[l].x));
            ap[1] = __uint_as_float(f2tf32(pa[l].y));
            ap[2] = __uint_as_float(f2tf32(pa[l].z));
            ap[3] = __uint_as_float(f2tf32(pa[l].w));
            int kk = idx >> 5, n4 = idx & 31;
            float* bp = &Bs[kk * BS_STRIDE + n4 * 4];
            bp[0] = __uint_as_float(f2tf32(pb[l].x));
            bp[1] = __uint_as_float(f2tf32(pb[l].y));
            bp[2] = __uint_as_float(f2tf32(pb[l].z));
            bp[3] = __uint_as_float(f2tf32(pb[l].w));
        }
        __syncthreads();

        // prefetch next tile
        if (k0 + 32 < K) {
#pragma unroll
            for (int l = 0; l < 4; l++) {
                int idx = tid + l * 256;
                int row = idx >> 3, c4 = idx & 7;
                pa[l] = *(const float4*)&A[(size_t)(mBase + row) * K + k0 + 32 + c4 * 4];
                int kk = idx >> 5, n4 = idx & 31;
                pb[l] = *(const float4*)&B[(size_t)(k0 + 32 + kk) * N + nBase + n4 * 4];
            }
        }

        // compute 4 k8 steps
#pragma unroll
        for (int kk8 = 0; kk8 < 4; kk8++) {
            const int kb = kk8 * 8;
            uint32_t a[4][4], b[4][2];
#pragma unroll
            for (int i = 0; i < 4; i++) {
                int row = wm + i * 16 + q;
                a[i][0] = __float_as_uint(As[(row)     * AS_STRIDE + kb + r]);
                a[i][1] = __float_as_uint(As[(row + 8) * AS_STRIDE + kb + r]);
                a[i][2] = __float_as_uint(As[(row)     * AS_STRIDE + kb + r + 4]);
                a[i][3] = __float_as_uint(As[(row + 8) * AS_STRIDE + kb + r + 4]);
            }
#pragma unroll
            for (int j = 0; j < 4; j++) {
                int col = wn + j * 8 + q;
                b[j][0] = __float_as_uint(Bs[(kb + r)     * BS_STRIDE + col]);
                b[j][1] = __float_as_uint(Bs[(kb + r + 4) * BS_STRIDE + col]);
            }
#pragma unroll
            for (int i = 0; i < 4; i++)
#pragma unroll
                for (int j = 0; j < 4; j++) {
                    asm volatile(
                        "mma.sync.aligned.m16n8k8.row.col.f32.tf32.tf32.f32 "
                        "{%0,%1,%2,%3}, {%4,%5,%6,%7}, {%8,%9}, {%0,%1,%2,%3};"
                        : "+f"(c[i][j][0]), "+f"(c[i][j][1]),
                          "+f"(c[i][j][2]), "+f"(c[i][j][3])
                        : "r"(a[i][0]), "r"(a[i][1]), "r"(a[i][2]), "r"(a[i][3]),
                          "r"(b[j][0]), "r"(b[j][1]));
                }
        }
        __syncthreads();
    }

    // epilogue: c0,c1 -> (row, 2r / 2r+1), c2,c3 -> (row+8, ...)
#pragma unroll
    for (int i = 0; i < 4; i++) {
        int row0 = mBase + wm + i * 16 + q;
#pragma unroll
        for (int j = 0; j < 4; j++) {
            int col = nBase + wn + j * 8 + 2 * r;
            float v0 = c[i][j][0], v1 = c[i][j][1];
            float v2 = c[i][j][2], v3 = c[i][j][3];
            if (RELU_BIAS) {
                float bb0 = bias[col], bb1 = bias[col + 1];
                v0 += bb0; v1 += bb1; v2 += bb0; v3 += bb1;
                v0 = v0 > 0.f ? v0 : 0.f; v1 = v1 > 0.f ? v1 : 0.f;
                v2 = v2 > 0.f ? v2 : 0.f; v3 = v3 > 0.f ? v3 : 0.f;
            }
            *(float2*)&C[(size_t)row0 * N + col]       = make_float2(v0, v1);
            *(float2*)&C[(size_t)(row0 + 8) * N + col] = make_float2(v2, v3);
        }
    }
}

// --------------------------- attention logits ---------------------------------
// gat1: 2 heads. g1[n, 0:256] is head0, g1[n, 256:512] is head1.
__global__ void al1_kernel(const float* __restrict__ a_src,
                           const float* __restrict__ a_dst)
{
    const float* g1 = g_g1;
    int n = blockIdx.x, t = threadIdx.x;  // 256 threads
    float v0 = g1[(size_t)n * D2 + t];
    float v1 = g1[(size_t)n * D2 + 256 + t];
    float s0 = v0 * a_src[t],       d0 = v0 * a_dst[t];
    float s1 = v1 * a_src[256 + t], d1 = v1 * a_dst[256 + t];
#pragma unroll
    for (int o = 16; o; o >>= 1) {
        s0 += __shfl_down_sync(0xffffffffu, s0, o);
        d0 += __shfl_down_sync(0xffffffffu, d0, o);
        s1 += __shfl_down_sync(0xffffffffu, s1, o);
        d1 += __shfl_down_sync(0xffffffffu, d1, o);
    }
    __shared__ float sh[4][8];
    int w = t >> 5, l = t & 31;
    if (l == 0) { sh[0][w] = s0; sh[1][w] = d0; sh[2][w] = s1; sh[3][w] = d1; }
    __syncthreads();
    if (t < 4) {
        float acc = 0.f;
#pragma unroll
        for (int w2 = 0; w2 < 8; w2++) acc += sh[t][w2];
        if (t == 0) g_al1s[n * 2 + 0] = acc;
        if (t == 1) g_al1d[n * 2 + 0] = acc;
        if (t == 2) g_al1s[n * 2 + 1] = acc;
        if (t == 3) g_al1d[n * 2 + 1] = acc;
    }
}

// gat2: 1 head over 512 channels.
__global__ void al2_kernel(const float* __restrict__ a_src,
                           const float* __restrict__ a_dst)
{
    const float* g2 = g_g2;
    int n = blockIdx.x, t = threadIdx.x;  // 256 threads
    float v0 = g2[(size_t)n * D2 + t];
    float v1 = g2[(size_t)n * D2 + 256 + t];
    float s = v0 * a_src[t] + v1 * a_src[256 + t];
    float d = v0 * a_dst[t] + v1 * a_dst[256 + t];
#pragma unroll
    for (int o = 16; o; o >>= 1) {
        s += __shfl_down_sync(0xffffffffu, s, o);
        d += __shfl_down_sync(0xffffffffu, d, o);
    }
    __shared__ float sh[2][8];
    int w = t >> 5, l = t & 31;
    if (l == 0) { sh[0][w] = s; sh[1][w] = d; }
    __syncthreads();
    if (t < 2) {
        float acc = 0.f;
#pragma unroll
        for (int w2 = 0; w2 < 8; w2++) acc += sh[t][w2];
        if (t == 0) g_al2s[n] = acc;
        else        g_al2d[n] = acc;
    }
}

// --------------------------- GAT aggregation ----------------------------------
// Softmax without max subtraction: logits are O(+-5), exp cannot overflow, and
// alpha is mathematically identical. One CTA (256 threads) per dst node.
__global__ void gat1_agg(const float* __restrict__ bias)  // b1[512] -> g_out1
{
    const float* h = g_g1;
    float* out = g_out1;
    int d = blockIdx.x, t = threadIdx.x;
    __shared__ float sw0[256], sw1[256];
    __shared__ int   ss[256];
    int start = g_off[d], end = g_off[d + 1];
    float ad0 = g_al1d[d * 2 + 0], ad1 = g_al1d[d * 2 + 1];
    float acc0 = 0.f, acc1 = 0.f, den0 = 0.f, den1 = 0.f;
    for (int base = start; base < end; base += 256) {
        int m = min(256, end - base);
        if (t < m) {
            int s = g_esrc[base + t];
            float e0 = g_al1s[s * 2 + 0] + ad0; e0 = e0 > 0.f ? e0 : 0.2f * e0;
            float e1 = g_al1s[s * 2 + 1] + ad1; e1 = e1 > 0.f ? e1 : 0.2f * e1;
            sw0[t] = __expf(e0);
            sw1[t] = __expf(e1);
            ss[t] = s;
        }
        __syncthreads();
        for (int j = 0; j < m; j++) {
            int s = ss[j];
            float w0 = sw0[j], w1 = sw1[j];
            acc0 += w0 * h[(size_t)s * D2 + t];
            acc1 += w1 * h[(size_t)s * D2 + 256 + t];
            den0 += w0; den1 += w1;
        }
        __syncthreads();
    }
    float o0 = acc0 / (den0 + 1e-16f) + bias[t];
    float o1 = acc1 / (den1 + 1e-16f) + bias[256 + t];
    out[(size_t)d * D2 + t]       = o0 > 0.f ? o0 : 0.f;
    out[(size_t)d * D2 + 256 + t] = o1 > 0.f ? o1 : 0.f;
}

__global__ void gat2_agg(const float* __restrict__ bias,  // b2[512]
                         float* __restrict__ out)         // d_out (relu applied)
{
    const float* h = g_g2;
    int d = blockIdx.x, t = threadIdx.x;
    __shared__ float sw[256];
    __shared__ int   ss[256];
    int start = g_off[d], end = g_off[d + 1];
    float ad = g_al2d[d];
    float acc0 = 0.f, acc1 = 0.f, den = 0.f;
    for (int base = start; base < end; base += 256) {
        int m = min(256, end - base);
        if (t < m) {
            int s = g_esrc[base + t];
            float e = g_al2s[s] + ad; e = e > 0.f ? e : 0.2f * e;
            sw[t] = __expf(e);
            ss[t] = s;
        }
        __syncthreads();
        for (int j = 0; j < m; j++) {
            int s = ss[j];
            float w = sw[j];
            acc0 += w * h[(size_t)s * D2 + t];
            acc1 += w * h[(size_t)s * D2 + 256 + t];
            den += w;
        }
        __syncthreads();
    }
    float r = 1.f / (den + 1e-16f);
    float o0 = acc0 * r + bias[t];
    float o1 = acc1 * r + bias[256 + t];
    out[(size_t)d * D2 + t]       = o0 > 0.f ? o0 : 0.f;
    out[(size_t)d * D2 + 256 + t] = o1 > 0.f ? o1 : 0.f;
}

// ------------------------------- launch ---------------------------------------
extern "C" void kernel_launch(void* const* d_in, const int* in_sizes, int n_in,
                              void* d_out, int out_size)
{
    const float* x     = (const float*)d_in[0];
    const int*   adj   = (const int*)d_in[1];     // int32 (JAX x64 disabled)
    const float* W_fc  = (const float*)d_in[2];
    const float* b_fc  = (const float*)d_in[3];
    const float* W1    = (const float*)d_in[4];
    const float* a1s   = (const float*)d_in[5];
    const float* a1d   = (const float*)d_in[6];
    const float* b1    = (const float*)d_in[7];
    const float* W2    = (const float*)d_in[8];
    const float* a2s   = (const float*)d_in[9];
    const float* a2d   = (const float*)d_in[10];
    const float* b2    = (const float*)d_in[11];
    float*       out   = (float*)d_out;

    // CSR build
    zero_kernel<<<64, 256>>>();
    hist_kernel<<<(E_TOT + 255) / 256, 256>>>(adj);
    scan_kernel<<<1, 1024>>>();
    scatter_kernel<<<(E_TOT + 255) / 256, 256>>>(adj);

    // fc: g_h0 = relu(x @ W_fc + b_fc)   [16384,256]
    gemm_tf32<1><<<dim3(H1 / 128, N_NODES / 128), 256>>>(x, -1, W_fc, b_fc, 0,
                                                         N_NODES, H1, H1);
    // gat1 features: g_g1 = g_h0 @ W1    [16384,512]
    gemm_tf32<0><<<dim3(D2 / 128, N_NODES / 128), 256>>>(nullptr, 0, W1, nullptr, 1,
                                                         N_NODES, D2, H1);
    al1_kernel<<<N_NODES, 256>>>(a1s, a1d);
    gat1_agg<<<N_NODES, 256>>>(b1);

    // gat2 features: g_g2 = g_out1 @ W2  [16384,512]
    gemm_tf32<0><<<dim3(D2 / 128, N_NODES / 128), 256>>>(nullptr, 2, W2, nullptr, 3,
                                                         N_NODES, D2, D2);
    al2_kernel<<<N_NODES, 256>>>(a2s, a2d);
    gat2_agg<<<N_NODES, 256>>>(b2, out);
}

// round 10
// speedup vs baseline: 2.3805x; 1.1341x over previous
#include <cuda_runtime.h>
#include <cuda_bf16.h>
#include <cstdint>

#define N_NODES 16384
#define E_RAW   262144
#define E_TOT   (E_RAW + N_NODES)   // 278528 with self loops
#define H1      256
#define D2      512                  // 2*H1 = gat1 out channels = gat2 channels

// ---------------- scratch (device globals; no allocation allowed) -------------
__device__ float g_h0  [N_NODES * H1];   // fc output (relu)
__device__ float g_g1  [N_NODES * D2];   // gat1 pre-agg features
__device__ float g_out1[N_NODES * D2];   // gat1 output (relu)
__device__ float g_g2  [N_NODES * D2];   // gat2 pre-agg features
__device__ float g_al1s[N_NODES * 2];
__device__ float g_al1d[N_NODES * 2];
__device__ float g_al2s[N_NODES];
__device__ float g_al2d[N_NODES];
__device__ int   g_deg [N_NODES];
__device__ int   g_cur [N_NODES];
__device__ int   g_off [N_NODES + 1];
__device__ int   g_esrc[E_TOT];

__device__ __forceinline__ float* buf_sel(int id) {
    switch (id) {
        case 0: return g_h0;
        case 1: return g_g1;
        case 2: return g_out1;
        case 3: return g_g2;
    }
    return nullptr;
}

// ------------------------------- CSR build -----------------------------------
__global__ void zero_kernel() {
    int i = blockIdx.x * blockDim.x + threadIdx.x;
    if (i < N_NODES) {
        g_deg[i] = 0; g_cur[i] = 0;
        g_al1s[2 * i] = 0.f; g_al1s[2 * i + 1] = 0.f;
        g_al1d[2 * i] = 0.f; g_al1d[2 * i + 1] = 0.f;
        g_al2s[i] = 0.f;     g_al2d[i] = 0.f;
    }
}

// adj is int32: adj[0..E_RAW) = src, adj[E_RAW..2*E_RAW) = dst
__global__ void hist_kernel(const int* __restrict__ adj) {
    int i = blockIdx.x * blockDim.x + threadIdx.x;
    if (i >= E_TOT) return;
    int dst = (i < E_RAW) ? adj[E_RAW + i] : (i - E_RAW);
    atomicAdd(&g_deg[dst], 1);
}

__global__ void scan_kernel() {
    __shared__ int partial[1024];
    int t = threadIdx.x;
    int base = t * 16;
    int local[16];
    int s = 0;
#pragma unroll
    for (int i = 0; i < 16; i++) { local[i] = s; s += g_deg[base + i]; }
    partial[t] = s;
    __syncthreads();
    for (int off = 1; off < 1024; off <<= 1) {
        int v = (t >= off) ? partial[t - off] : 0;
        __syncthreads();
        partial[t] += v;
        __syncthreads();
    }
    int pre = (t == 0) ? 0 : partial[t - 1];
#pragma unroll
    for (int i = 0; i < 16; i++) g_off[base + i] = pre + local[i];
    if (t == 1023) g_off[N_NODES] = partial[1023];
}

__global__ void scatter_kernel(const int* __restrict__ adj) {
    int i = blockIdx.x * blockDim.x + threadIdx.x;
    if (i >= E_TOT) return;
    int src, dst;
    if (i < E_RAW) { src = adj[i]; dst = adj[E_RAW + i]; }
    else           { src = i - E_RAW;  dst = i - E_RAW; }
    int pos = g_off[dst] + atomicAdd(&g_cur[dst], 1);
    g_esrc[pos] = src;
}

// --------------------------- TF32 tensor-core GEMM ----------------------------
// C[M,N] = A[M,K] * B[K,N], row-major. M%128==0, N%128==0, K%32==0.
// CTA tile 128x128, 8 warps, warp tile 64x32, mma.sync m16n8k8 tf32.
// AL_MODE 1: fused gat1 logit partials (2 heads). AL_MODE 2: gat2 (1 head).
__device__ __forceinline__ uint32_t f2tf32(float x) {
    uint32_t u;
    asm("cvt.rna.tf32.f32 %0, %1;" : "=r"(u) : "f"(x));
    return u;
}

#define AS_STRIDE 36
#define BS_STRIDE 136

template <int RELU_BIAS, int AL_MODE>
__global__ __launch_bounds__(256) void gemm_tf32(
    const float* __restrict__ A_ext, int a_sel,
    const float* __restrict__ B,
    const float* __restrict__ bias, int c_sel,
    const float* __restrict__ a_s, const float* __restrict__ a_d,
    int M, int N, int K)
{
    const float* A = (a_sel < 0) ? A_ext : buf_sel(a_sel);
    float* C = buf_sel(c_sel);

    __shared__ float As[128 * AS_STRIDE];   // [m][k], k-step 32, pad->36
    __shared__ float Bs[32 * BS_STRIDE];    // [k][n], n 128, pad->136

    const int tid  = threadIdx.x;
    const int lane = tid & 31;
    const int wid  = tid >> 5;
    const int q = lane >> 2;     // 0..7
    const int r = lane & 3;      // 0..3
    const int wm = (wid >> 2) * 64;   // warp m offset: 0 or 64
    const int wn = (wid & 3) * 32;    // warp n offset: 0,32,64,96

    const int mBase = blockIdx.y * 128, nBase = blockIdx.x * 128;

    float c[4][4][4];
#pragma unroll
    for (int i = 0; i < 4; i++)
#pragma unroll
        for (int j = 0; j < 4; j++)
#pragma unroll
            for (int u = 0; u < 4; u++) c[i][j][u] = 0.f;

    float4 pa[4], pb[4];
#pragma unroll
    for (int l = 0; l < 4; l++) {
        int idx = tid + l * 256;
        int row = idx >> 3, c4 = idx & 7;
        pa[l] = *(const float4*)&A[(size_t)(mBase + row) * K + c4 * 4];
        int kk = idx >> 5, n4 = idx & 31;
        pb[l] = *(const float4*)&B[(size_t)kk * N + nBase + n4 * 4];
    }

    for (int k0 = 0; k0 < K; k0 += 32) {
#pragma unroll
        for (int l = 0; l < 4; l++) {
            int idx = tid + l * 256;
            int row = idx >> 3, c4 = idx & 7;
            float* ap = &As[row * AS_STRIDE + c4 * 4];
            ap[0] = __uint_as_float(f2tf32(pa[l].x));
            ap[1] = __uint_as_float(f2tf32(pa[l].y));
            ap[2] = __uint_as_float(f2tf32(pa[l].z));
            ap[3] = __uint_as_float(f2tf32(pa[l].w));
            int kk = idx >> 5, n4 = idx & 31;
            float* bp = &Bs[kk * BS_STRIDE + n4 * 4];
            bp[0] = __uint_as_float(f2tf32(pb[l].x));
            bp[1] = __uint_as_float(f2tf32(pb[l].y));
            bp[2] = __uint_as_float(f2tf32(pb[l].z));
            bp[3] = __uint_as_float(f2tf32(pb[l].w));
        }
        __syncthreads();

        if (k0 + 32 < K) {
#pragma unroll
            for (int l = 0; l < 4; l++) {
                int idx = tid + l * 256;
                int row = idx >> 3, c4 = idx & 7;
                pa[l] = *(const float4*)&A[(size_t)(mBase + row) * K + k0 + 32 + c4 * 4];
                int kk = idx >> 5, n4 = idx & 31;
                pb[l] = *(const float4*)&B[(size_t)(k0 + 32 + kk) * N + nBase + n4 * 4];
            }
        }

#pragma unroll
        for (int kk8 = 0; kk8 < 4; kk8++) {
            const int kb = kk8 * 8;
            uint32_t a[4][4], b[4][2];
#pragma unroll
            for (int i = 0; i < 4; i++) {
                int row = wm + i * 16 + q;
                a[i][0] = __float_as_uint(As[(row)     * AS_STRIDE + kb + r]);
                a[i][1] = __float_as_uint(As[(row + 8) * AS_STRIDE + kb + r]);
                a[i][2] = __float_as_uint(As[(row)     * AS_STRIDE + kb + r + 4]);
                a[i][3] = __float_as_uint(As[(row + 8) * AS_STRIDE + kb + r + 4]);
            }
#pragma unroll
            for (int j = 0; j < 4; j++) {
                int col = wn + j * 8 + q;
                b[j][0] = __float_as_uint(Bs[(kb + r)     * BS_STRIDE + col]);
                b[j][1] = __float_as_uint(Bs[(kb + r + 4) * BS_STRIDE + col]);
            }
#pragma unroll
            for (int i = 0; i < 4; i++)
#pragma unroll
                for (int j = 0; j < 4; j++) {
                    asm volatile(
                        "mma.sync.aligned.m16n8k8.row.col.f32.tf32.tf32.f32 "
                        "{%0,%1,%2,%3}, {%4,%5,%6,%7}, {%8,%9}, {%0,%1,%2,%3};"
                        : "+f"(c[i][j][0]), "+f"(c[i][j][1]),
                          "+f"(c[i][j][2]), "+f"(c[i][j][3])
                        : "r"(a[i][0]), "r"(a[i][1]), "r"(a[i][2]), "r"(a[i][3]),
                          "r"(b[j][0]), "r"(b[j][1]));
                }
        }
        __syncthreads();
    }

    // epilogue (+ optional fused attention-logit partial sums)
    float ps[4][2], pd[4][2];
    if (AL_MODE) {
#pragma unroll
        for (int i = 0; i < 4; i++) {
            ps[i][0] = ps[i][1] = 0.f;
            pd[i][0] = pd[i][1] = 0.f;
        }
    }

#pragma unroll
    for (int i = 0; i < 4; i++) {
        int row0 = mBase + wm + i * 16 + q;
#pragma unroll
        for (int j = 0; j < 4; j++) {
            int col = nBase + wn + j * 8 + 2 * r;
            float v0 = c[i][j][0], v1 = c[i][j][1];
            float v2 = c[i][j][2], v3 = c[i][j][3];
            if (RELU_BIAS) {
                float bb0 = bias[col], bb1 = bias[col + 1];
                v0 += bb0; v1 += bb1; v2 += bb0; v3 += bb1;
                v0 = v0 > 0.f ? v0 : 0.f; v1 = v1 > 0.f ? v1 : 0.f;
                v2 = v2 > 0.f ? v2 : 0.f; v3 = v3 > 0.f ? v3 : 0.f;
            }
            if (AL_MODE) {
                float as0 = a_s[col], as1 = a_s[col + 1];
                float ad0 = a_d[col], ad1 = a_d[col + 1];
                ps[i][0] += v0 * as0 + v1 * as1;
                pd[i][0] += v0 * ad0 + v1 * ad1;
                ps[i][1] += v2 * as0 + v3 * as1;
                pd[i][1] += v2 * ad0 + v3 * ad1;
            }
            *(float2*)&C[(size_t)row0 * N + col]       = make_float2(v0, v1);
            *(float2*)&C[(size_t)(row0 + 8) * N + col] = make_float2(v2, v3);
        }
    }

    if (AL_MODE) {
#pragma unroll
        for (int i = 0; i < 4; i++) {
#pragma unroll
            for (int half = 0; half < 2; half++) {
                float s = ps[i][half], dd = pd[i][half];
                s  += __shfl_xor_sync(0xffffffffu, s, 1);
                s  += __shfl_xor_sync(0xffffffffu, s, 2);
                dd += __shfl_xor_sync(0xffffffffu, dd, 1);
                dd += __shfl_xor_sync(0xffffffffu, dd, 2);
                if (r == 0) {
                    int row = mBase + wm + i * 16 + q + half * 8;
                    if (AL_MODE == 1) {
                        int head = ((nBase + wn) >> 8) & 1;
                        atomicAdd(&g_al1s[row * 2 + head], s);
                        atomicAdd(&g_al1d[row * 2 + head], dd);
                    } else {
                        atomicAdd(&g_al2s[row], s);
                        atomicAdd(&g_al2d[row], dd);
                    }
                }
            }
        }
    }
}

// --------------------------- GAT aggregation ----------------------------------
// Softmax without max subtraction: self-loops guarantee nonempty segments and
// glorot-scale logits are O(+-5) -> exp cannot overflow; alpha identical.
// One CTA (256 threads) per dst node; thread t owns channels 2t, 2t+1.
__global__ void gat1_agg(const float* __restrict__ bias)  // b1[512] -> g_out1
{
    const float* h = g_g1;
    float* out = g_out1;
    int d = blockIdx.x, t = threadIdx.x;
    __shared__ float sw0[256], sw1[256];
    __shared__ int   ss[256];
    int start = g_off[d], end = g_off[d + 1];
    float ad0 = g_al1d[d * 2 + 0], ad1 = g_al1d[d * 2 + 1];
    float accx = 0.f, accy = 0.f, den = 0.f;
    const int ch = 2 * t;                 // channels ch, ch+1 (same head)
    const bool head1 = (t >= 128);
    for (int base = start; base < end; base += 256) {
        int m = min(256, end - base);
        if (t < m) {
            int s = g_esrc[base + t];
            float e0 = g_al1s[s * 2 + 0] + ad0; e0 = e0 > 0.f ? e0 : 0.2f * e0;
            float e1 = g_al1s[s * 2 + 1] + ad1; e1 = e1 > 0.f ? e1 : 0.2f * e1;
            sw0[t] = __expf(e0);
            sw1[t] = __expf(e1);
            ss[t] = s;
        }
        __syncthreads();
        for (int j = 0; j < m; j++) {
            int s = ss[j];
            float w = head1 ? sw1[j] : sw0[j];
            float2 hv = *(const float2*)&h[(size_t)s * D2 + ch];
            accx += w * hv.x;
            accy += w * hv.y;
            den += w;
        }
        __syncthreads();
    }
    float rden = 1.f / (den + 1e-16f);
    float2 bb = *(const float2*)&bias[ch];
    float o0 = accx * rden + bb.x;
    float o1 = accy * rden + bb.y;
    o0 = o0 > 0.f ? o0 : 0.f;
    o1 = o1 > 0.f ? o1 : 0.f;
    *(float2*)&out[(size_t)d * D2 + ch] = make_float2(o0, o1);
}

__global__ void gat2_agg(const float* __restrict__ bias,  // b2[512]
                         float* __restrict__ out)         // d_out (relu applied)
{
    const float* h = g_g2;
    int d = blockIdx.x, t = threadIdx.x;
    __shared__ float sw[256];
    __shared__ int   ss[256];
    int start = g_off[d], end = g_off[d + 1];
    float ad = g_al2d[d];
    float accx = 0.f, accy = 0.f, den = 0.f;
    const int ch = 2 * t;
    for (int base = start; base < end; base += 256) {
        int m = min(256, end - base);
        if (t < m) {
            int s = g_esrc[base + t];
            float e = g_al2s[s] + ad; e = e > 0.f ? e : 0.2f * e;
            sw[t] = __expf(e);
            ss[t] = s;
        }
        __syncthreads();
        for (int j = 0; j < m; j++) {
            int s = ss[j];
            float w = sw[j];
            float2 hv = *(const float2*)&h[(size_t)s * D2 + ch];
            accx += w * hv.x;
            accy += w * hv.y;
            den += w;
        }
        __syncthreads();
    }
    float rden = 1.f / (den + 1e-16f);
    float2 bb = *(const float2*)&bias[ch];
    float o0 = accx * rden + bb.x;
    float o1 = accy * rden + bb.y;
    o0 = o0 > 0.f ? o0 : 0.f;
    o1 = o1 > 0.f ? o1 : 0.f;
    *(float2*)&out[(size_t)d * D2 + ch] = make_float2(o0, o1);
}

// ------------------------------- launch ---------------------------------------
extern "C" void kernel_launch(void* const* d_in, const int* in_sizes, int n_in,
                              void* d_out, int out_size)
{
    const float* x     = (const float*)d_in[0];
    const int*   adj   = (const int*)d_in[1];     // int32 (JAX x64 disabled)
    const float* W_fc  = (const float*)d_in[2];
    const float* b_fc  = (const float*)d_in[3];
    const float* W1    = (const float*)d_in[4];
    const float* a1s   = (const float*)d_in[5];
    const float* a1d   = (const float*)d_in[6];
    const float* b1    = (const float*)d_in[7];
    const float* W2    = (const float*)d_in[8];
    const float* a2s   = (const float*)d_in[9];
    const float* a2d   = (const float*)d_in[10];
    const float* b2    = (const float*)d_in[11];
    float*       out   = (float*)d_out;

    // CSR build + logit zeroing
    zero_kernel<<<64, 256>>>();
    hist_kernel<<<(E_TOT + 255) / 256, 256>>>(adj);
    scan_kernel<<<1, 1024>>>();
    scatter_kernel<<<(E_TOT + 255) / 256, 256>>>(adj);

    // fc: g_h0 = relu(x @ W_fc + b_fc)   [16384,256]
    gemm_tf32<1, 0><<<dim3(H1 / 128, N_NODES / 128), 256>>>(
        x, -1, W_fc, b_fc, 0, nullptr, nullptr, N_NODES, H1, H1);
    // gat1 features: g_g1 = g_h0 @ W1    [16384,512]  (+ fused al1 logits)
    gemm_tf32<0, 1><<<dim3(D2 / 128, N_NODES / 128), 256>>>(
        nullptr, 0, W1, nullptr, 1, a1s, a1d, N_NODES, D2, H1);
    gat1_agg<<<N_NODES, 256>>>(b1);

    // gat2 features: g_g2 = g_out1 @ W2  [16384,512]  (+ fused al2 logits)
    gemm_tf32<0, 2><<<dim3(D2 / 128, N_NODES / 128), 256>>>(
        nullptr, 2, W2, nullptr, 3, a2s, a2d, N_NODES, D2, D2);
    gat2_agg<<<N_NODES, 256>>>(b2, out);
}